// round 4
// baseline (speedup 1.0000x reference)
#include <cuda_runtime.h>
#include <cuda_fp16.h>
#include <stdint.h>
#include <math.h>

#define NB 256   // batch
#define NI 128   // input capsules
#define DD 256   // input feature dim
#define NO 32    // output capsules
#define HH 64    // in_dim == out_dim

// ---- scratch (device globals; no allocation allowed) ----
__device__ __half g_votes[(size_t)NB * NI * NO * HH];  // [n][i][o][h] fp16, 134 MB
__device__ __half g_uh[(size_t)NB * NI * HH];          // squashed u fp16, 4 MB
__device__ float  g_ai[NB * NI];                       // ||u||
__device__ float  g_b[(size_t)NB * NI * NO];           // routing logits (iter-2 b)
__device__ float  g_v[(size_t)NB * NO * HH];           // per-iter output caps
__device__ float  g_spart[2ull * NB * NO * HH];        // partial sums (2 i-halves)

__device__ __forceinline__ uint32_t smem_u32(const void* p) {
    uint32_t a;
    asm("{ .reg .u64 t; cvta.to.shared.u64 t, %1; cvt.u32.u64 %0, t; }" : "=r"(a) : "l"(p));
    return a;
}

// ============================================================
// K1: u[n,i,h] = squash( x[n,i,:] @ Wcap[i] + Bcap[i] ) -> fp16, ai = ||u||
// ============================================================
__global__ __launch_bounds__(256) void k_u(const float* __restrict__ x,
                                           const float* __restrict__ Wcap,
                                           const float* __restrict__ Bcap) {
    const int i  = blockIdx.y;
    const int n0 = blockIdx.x * 32;
    const int t  = threadIdx.x;
    const int h  = t & 63;
    const int ns = t >> 6;
    const int lane = t & 31, warp = t >> 5;

    __shared__ float sx[4 * 256];
    __shared__ float spart[8];

    const float bc = Bcap[i * HH + h];
    const float* wp = Wcap + (size_t)i * DD * HH + h;

    for (int ch = 0; ch < 8; ++ch) {
        const int nb = n0 + ch * 4;
        __syncthreads();
        #pragma unroll
        for (int idx = t; idx < 1024; idx += 256)
            sx[idx] = x[((size_t)(nb + (idx >> 8)) * NI + i) * DD + (idx & 255)];
        __syncthreads();

        float acc = bc;
        const float* xp = sx + ns * 256;
        #pragma unroll 8
        for (int d = 0; d < DD; ++d)
            acc += xp[d] * wp[(size_t)d * HH];

        float sq = acc * acc;
        #pragma unroll
        for (int off = 16; off; off >>= 1) sq += __shfl_xor_sync(0xffffffffu, sq, off);
        if (lane == 0) spart[warp] = sq;
        __syncthreads();
        const float n2  = spart[ns * 2] + spart[ns * 2 + 1];
        const float nrm = sqrtf(n2);
        const float f   = (n2 / (n2 + 1.0f)) / (nrm + 1e-8f);
        const int n = nb + ns;
        g_uh[((size_t)n * NI + i) * HH + h] = __float2half(acc * f);
        if (h == 0) g_ai[n * NI + i] = f * nrm;
    }
}

// ============================================================
// K2 (HMMA): votes[n,i,o,h] = fp16( mask * (u[:,i] @ Wv[i,o] + Bv) )
// block = (o, i), 128 threads / 4 warps. M=256 (n), N=64 (h), K=64 (d).
// A = u[:,i,:] fp16 smem (XOR-swizzled 16B chunks), B = Wv[i,o] fp32->fp16.
// Warp w computes rows 64w..64w+63 via mma.m16n8k16 (4 mt x 8 nt x 4 k).
// ============================================================
__global__ __launch_bounds__(128) void k_votes(const float* __restrict__ Wv,
                                               const float* __restrict__ Bv,
                                               const float* __restrict__ mask) {
    __shared__ __align__(16) unsigned char sm[41216];
    const int o = blockIdx.x, i = blockIdx.y;
    const int t = threadIdx.x, wid = t >> 5, lane = t & 31;
    __half* sA = reinterpret_cast<__half*>(sm);           // 256 x 64 (32 KB)
    __half* sB = reinterpret_cast<__half*>(sm + 32768);   // 64 x 64  (8 KB)
    float*  sbv = reinterpret_cast<float*>(sm + 40960);   // bias (256 B)

    // ---- load A: u[:, i, :] as 16B chunks, chunk ^= (row & 7)
    const uint4* usrc = reinterpret_cast<const uint4*>(g_uh) + (size_t)i * 8;
    #pragma unroll
    for (int idx = t; idx < 2048; idx += 128) {
        const int n = idx >> 3, c = idx & 7;
        uint4 v = usrc[(size_t)n * (NI * 8) + c];
        reinterpret_cast<uint4*>(sA)[n * 8 + (c ^ (n & 7))] = v;
    }
    // ---- load B: Wv[i,o][d][h] fp32 -> fp16, same chunk swizzle per row d
    const float2* wsrc = reinterpret_cast<const float2*>(Wv + ((size_t)(i * NO + o) << 12));
    #pragma unroll
    for (int idx = t; idx < 2048; idx += 128) {
        const int d = idx >> 5, hp = idx & 31;     // hp = half2 index within row
        const float2 f = wsrc[idx];
        const __half2 hv = __floats2half2_rn(f.x, f.y);
        const int c = hp >> 2, w_ = hp & 3;
        reinterpret_cast<__half2*>(sB)[d * 32 + ((c ^ (d & 7)) << 2) + w_] = hv;
    }
    if (t < 64) sbv[t] = Bv[(i * NO + o) * HH + t];
    __syncthreads();

    float acc[4][8][4];
    #pragma unroll
    for (int mt = 0; mt < 4; ++mt)
        #pragma unroll
        for (int nt = 0; nt < 8; ++nt) {
            acc[mt][nt][0] = 0.f; acc[mt][nt][1] = 0.f;
            acc[mt][nt][2] = 0.f; acc[mt][nt][3] = 0.f;
        }

    const uint32_t sA32 = smem_u32(sA);
    const uint32_t sB32 = smem_u32(sB);

    #pragma unroll
    for (int k = 0; k < 4; ++k) {
        uint32_t a[4][4];
        #pragma unroll
        for (int mt = 0; mt < 4; ++mt) {
            const int row = wid * 64 + mt * 16 + (lane & 15);
            const int ch  = (k * 2 + (lane >> 4)) ^ (row & 7);
            const uint32_t addr = sA32 + row * 128 + ch * 16;
            asm volatile("ldmatrix.sync.aligned.m8n8.x4.shared.b16 {%0,%1,%2,%3}, [%4];"
                : "=r"(a[mt][0]), "=r"(a[mt][1]), "=r"(a[mt][2]), "=r"(a[mt][3]) : "r"(addr));
        }
        uint32_t b[8][2];
        #pragma unroll
        for (int nt = 0; nt < 8; ++nt) {
            const int d  = k * 16 + (lane & 15);   // threads 0-15 supply addresses
            const int ch = nt ^ (d & 7);
            const uint32_t addr = sB32 + d * 128 + ch * 16;
            asm volatile("ldmatrix.sync.aligned.m8n8.x2.trans.shared.b16 {%0,%1}, [%2];"
                : "=r"(b[nt][0]), "=r"(b[nt][1]) : "r"(addr));
        }
        #pragma unroll
        for (int mt = 0; mt < 4; ++mt)
            #pragma unroll
            for (int nt = 0; nt < 8; ++nt)
                asm volatile("mma.sync.aligned.m16n8k16.row.col.f32.f16.f16.f32 "
                    "{%0,%1,%2,%3}, {%4,%5,%6,%7}, {%8,%9}, {%0,%1,%2,%3};"
                    : "+f"(acc[mt][nt][0]), "+f"(acc[mt][nt][1]),
                      "+f"(acc[mt][nt][2]), "+f"(acc[mt][nt][3])
                    : "r"(a[mt][0]), "r"(a[mt][1]), "r"(a[mt][2]), "r"(a[mt][3]),
                      "r"(b[nt][0]), "r"(b[nt][1]));
    }
    __syncthreads();   // everyone done reading sA/sB

    // ---- stage (bias added), row stride 72 halfs -> conflict-free
    __half2* stg = reinterpret_cast<__half2*>(sm);
    #pragma unroll
    for (int mt = 0; mt < 4; ++mt) {
        const int r0 = wid * 64 + mt * 16 + (lane >> 2);
        #pragma unroll
        for (int nt = 0; nt < 8; ++nt) {
            const int h = nt * 8 + (lane & 3) * 2;
            const float b0 = sbv[h], b1 = sbv[h + 1];
            stg[(r0 * 72 + h) >> 1] =
                __floats2half2_rn(acc[mt][nt][0] + b0, acc[mt][nt][1] + b1);
            stg[((r0 + 8) * 72 + h) >> 1] =
                __floats2half2_rn(acc[mt][nt][2] + b0, acc[mt][nt][3] + b1);
        }
    }
    __syncthreads();

    // ---- coalesced fp16 stores with mask applied
    #pragma unroll
    for (int p = 0; p < 16; ++p) {
        const int n = p * 16 + (t >> 3), c = t & 7;
        const __half2 mk2 = __float2half2_rn(mask[n * NI + i]);
        uint4 v = *reinterpret_cast<const uint4*>(sm + n * 144 + c * 16);
        __half2* vh = reinterpret_cast<__half2*>(&v);
        vh[0] = __hmul2(vh[0], mk2); vh[1] = __hmul2(vh[1], mk2);
        vh[2] = __hmul2(vh[2], mk2); vh[3] = __hmul2(vh[3], mk2);
        *reinterpret_cast<uint4*>(g_votes + ((size_t)(n * NI + i) * NO + o) * HH + c * 8) = v;
    }
}

// ============================================================
// K3 (fused routing pass): one streaming read of votes per iteration.
// block = (ihalf, n): per i: agree (iters 2,3) -> b -> softmax -> c,
// accumulate s += c * votes, write partial s.
// ============================================================
__global__ __launch_bounds__(256) void k_route(int iter) {
    const int ih = blockIdx.x, n = blockIdx.y;
    const int t = threadIdx.x, o = t >> 3, hg = t & 7;
    __shared__ __align__(16) float sv[NO * HH];
    __shared__ float sai[64], sb2[NO], sc[NO];

    if (iter > 1) {
        #pragma unroll
        for (int idx = t; idx < NO * HH; idx += 256) sv[idx] = g_v[(size_t)n * NO * HH + idx];
    }
    if (t < 64) sai[t] = g_ai[n * NI + ih * 64 + t];
    __syncthreads();

    float sr[8] = {0, 0, 0, 0, 0, 0, 0, 0};
    const uint4* vbase = reinterpret_cast<const uint4*>(
        g_votes + ((size_t)(n * NI + ih * 64)) * NO * HH);

    uint4 raw = vbase[t];
    for (int ii = 0; ii < 64; ++ii) {
        const uint4 cur = raw;
        if (ii < 63) raw = vbase[(size_t)(ii + 1) * 256 + t];

        const float2 f0 = __half22float2(*reinterpret_cast<const __half2*>(&cur.x));
        const float2 f1 = __half22float2(*reinterpret_cast<const __half2*>(&cur.y));
        const float2 f2 = __half22float2(*reinterpret_cast<const __half2*>(&cur.z));
        const float2 f3 = __half22float2(*reinterpret_cast<const __half2*>(&cur.w));

        float c;
        if (iter == 1) {
            c = sai[ii] * (1.0f / 33.0f);
        } else {
            const float4 va = *reinterpret_cast<const float4*>(sv + o * HH + hg * 8);
            const float4 vb = *reinterpret_cast<const float4*>(sv + o * HH + hg * 8 + 4);
            float p = f0.x * va.x + f0.y * va.y + f1.x * va.z + f1.y * va.w
                    + f2.x * vb.x + f2.y * vb.y + f3.x * vb.z + f3.y * vb.w;
            p += __shfl_xor_sync(0xffffffffu, p, 1);
            p += __shfl_xor_sync(0xffffffffu, p, 2);
            p += __shfl_xor_sync(0xffffffffu, p, 4);
            if (hg == 0) {
                const size_t bidx = ((size_t)(n * NI + ih * 64 + ii)) * NO + o;
                float b = p + (iter == 2 ? 0.0f : g_b[bidx]);
                if (iter == 2) g_b[bidx] = b;
                sb2[o] = b;
            }
            __syncthreads();
            if (t < 32) {
                const float b = sb2[t];
                float m = b;
                #pragma unroll
                for (int off = 16; off; off >>= 1) m = fmaxf(m, __shfl_xor_sync(0xffffffffu, m, off));
                m = fmaxf(m, 0.0f);
                const float e = __expf(b - m);
                float s = e;
                #pragma unroll
                for (int off = 16; off; off >>= 1) s += __shfl_xor_sync(0xffffffffu, s, off);
                s += __expf(-m);
                sc[t] = sai[ii] * e / s;
            }
            __syncthreads();
            c = sc[o];
        }
        sr[0] += c * f0.x; sr[1] += c * f0.y; sr[2] += c * f1.x; sr[3] += c * f1.y;
        sr[4] += c * f2.x; sr[5] += c * f2.y; sr[6] += c * f3.x; sr[7] += c * f3.y;
    }

    float* dst = g_spart + ((size_t)(ih * NB + n) * NO + o) * HH + hg * 8;
    *reinterpret_cast<float4*>(dst)     = make_float4(sr[0], sr[1], sr[2], sr[3]);
    *reinterpret_cast<float4*>(dst + 4) = make_float4(sr[4], sr[5], sr[6], sr[7]);
}

// ============================================================
// K4: combine 2 partials, squash over h, write v (or final out).
// ============================================================
__global__ __launch_bounds__(256) void k_fin(int last, float* __restrict__ out) {
    const int n = blockIdx.x;
    const int t = threadIdx.x, o = t >> 3, hg = t & 7;
    const size_t base = ((size_t)n * NO + o) * HH + hg * 8;
    const size_t half2off = (size_t)NB * NO * HH;

    const float4 a0 = *reinterpret_cast<const float4*>(g_spart + base);
    const float4 a1 = *reinterpret_cast<const float4*>(g_spart + base + 4);
    const float4 b0 = *reinterpret_cast<const float4*>(g_spart + half2off + base);
    const float4 b1 = *reinterpret_cast<const float4*>(g_spart + half2off + base + 4);

    float s[8] = {a0.x + b0.x, a0.y + b0.y, a0.z + b0.z, a0.w + b0.w,
                  a1.x + b1.x, a1.y + b1.y, a1.z + b1.z, a1.w + b1.w};
    float q = 0.0f;
    #pragma unroll
    for (int j = 0; j < 8; ++j) q += s[j] * s[j];
    q += __shfl_xor_sync(0xffffffffu, q, 1);
    q += __shfl_xor_sync(0xffffffffu, q, 2);
    q += __shfl_xor_sync(0xffffffffu, q, 4);
    const float nrm = sqrtf(q);
    const float f = (q / (q + 1.0f)) / (nrm + 1e-8f);

    float* dst = (last ? out : g_v) + ((size_t)n * NO + o) * HH + hg * 8;
    #pragma unroll
    for (int j = 0; j < 8; ++j) dst[j] = s[j] * f;
}

// ============================================================
extern "C" void kernel_launch(void* const* d_in, const int* in_sizes, int n_in,
                              void* d_out, int out_size) {
    const float* x    = (const float*)d_in[0];
    const float* mask = (const float*)d_in[1];
    const float* Wcap = (const float*)d_in[2];
    const float* Bcap = (const float*)d_in[3];
    const float* Wv   = (const float*)d_in[4];
    const float* Bv   = (const float*)d_in[5];
    float* out = (float*)d_out;

    k_u    <<<dim3(8, 128),  256>>>(x, Wcap, Bcap);
    k_votes<<<dim3(NO, NI),  128>>>(Wv, Bv, mask);

    k_route<<<dim3(2, NB), 256>>>(1);
    k_fin  <<<NB, 256>>>(0, out);
    k_route<<<dim3(2, NB), 256>>>(2);
    k_fin  <<<NB, 256>>>(0, out);
    k_route<<<dim3(2, NB), 256>>>(3);
    k_fin  <<<NB, 256>>>(1, out);
}

// round 5
// speedup vs baseline: 1.0556x; 1.0556x over previous
#include <cuda_runtime.h>
#include <cuda_fp16.h>
#include <stdint.h>
#include <math.h>

#define NB 256   // batch
#define NI 128   // input capsules
#define DD 256   // input feature dim
#define NO 32    // output capsules
#define HH 64    // in_dim == out_dim

// ---- scratch (device globals; no allocation allowed) ----
__device__ __half g_votes[(size_t)NB * NI * NO * HH];  // [n][i][o][h] fp16, 134 MB
__device__ __half g_uh[(size_t)NB * NI * HH];          // squashed u fp16, 4 MB
__device__ float  g_ai[NB * NI];                       // ||u||
__device__ float  g_b[(size_t)NB * NI * NO];           // routing logits after iter-2

__device__ __forceinline__ uint32_t smem_u32(const void* p) {
    uint32_t a;
    asm("{ .reg .u64 t; cvta.to.shared.u64 t, %1; cvt.u32.u64 %0, t; }" : "=r"(a) : "l"(p));
    return a;
}

// ============================================================
// K1: u[n,i,h] = squash( x[n,i,:] @ Wcap[i] + Bcap[i] ) -> fp16, ai = ||u||
// ============================================================
__global__ __launch_bounds__(256) void k_u(const float* __restrict__ x,
                                           const float* __restrict__ Wcap,
                                           const float* __restrict__ Bcap) {
    const int i  = blockIdx.y;
    const int n0 = blockIdx.x * 32;
    const int t  = threadIdx.x;
    const int h  = t & 63;
    const int ns = t >> 6;
    const int lane = t & 31, warp = t >> 5;

    __shared__ float sx[4 * 256];
    __shared__ float spart[8];

    const float bc = Bcap[i * HH + h];
    const float* wp = Wcap + (size_t)i * DD * HH + h;

    for (int ch = 0; ch < 8; ++ch) {
        const int nb = n0 + ch * 4;
        __syncthreads();
        #pragma unroll
        for (int idx = t; idx < 1024; idx += 256)
            sx[idx] = x[((size_t)(nb + (idx >> 8)) * NI + i) * DD + (idx & 255)];
        __syncthreads();

        float acc = bc;
        const float* xp = sx + ns * 256;
        #pragma unroll 8
        for (int d = 0; d < DD; ++d)
            acc += xp[d] * wp[(size_t)d * HH];

        float sq = acc * acc;
        #pragma unroll
        for (int off = 16; off; off >>= 1) sq += __shfl_xor_sync(0xffffffffu, sq, off);
        if (lane == 0) spart[warp] = sq;
        __syncthreads();
        const float n2  = spart[ns * 2] + spart[ns * 2 + 1];
        const float nrm = sqrtf(n2);
        const float f   = (n2 / (n2 + 1.0f)) / (nrm + 1e-8f);
        const int n = nb + ns;
        g_uh[((size_t)n * NI + i) * HH + h] = __float2half(acc * f);
        if (h == 0) g_ai[n * NI + i] = f * nrm;
    }
}

// ============================================================
// K2 (HMMA): votes[n,i,o,h] = fp16( mask * (u[:,i] @ Wv[i,o] + Bv) )
// ============================================================
__global__ __launch_bounds__(128) void k_votes(const float* __restrict__ Wv,
                                               const float* __restrict__ Bv,
                                               const float* __restrict__ mask) {
    __shared__ __align__(16) unsigned char sm[41216];
    const int o = blockIdx.x, i = blockIdx.y;
    const int t = threadIdx.x, wid = t >> 5, lane = t & 31;
    __half* sA = reinterpret_cast<__half*>(sm);           // 256 x 64 (32 KB)
    __half* sB = reinterpret_cast<__half*>(sm + 32768);   // 64 x 64  (8 KB)
    float*  sbv = reinterpret_cast<float*>(sm + 40960);   // bias (256 B)

    const uint4* usrc = reinterpret_cast<const uint4*>(g_uh) + (size_t)i * 8;
    #pragma unroll
    for (int idx = t; idx < 2048; idx += 128) {
        const int n = idx >> 3, c = idx & 7;
        uint4 v = usrc[(size_t)n * (NI * 8) + c];
        reinterpret_cast<uint4*>(sA)[n * 8 + (c ^ (n & 7))] = v;
    }
    const float2* wsrc = reinterpret_cast<const float2*>(Wv + ((size_t)(i * NO + o) << 12));
    #pragma unroll
    for (int idx = t; idx < 2048; idx += 128) {
        const int d = idx >> 5, hp = idx & 31;
        const float2 f = wsrc[idx];
        const __half2 hv = __floats2half2_rn(f.x, f.y);
        const int c = hp >> 2, w_ = hp & 3;
        reinterpret_cast<__half2*>(sB)[d * 32 + ((c ^ (d & 7)) << 2) + w_] = hv;
    }
    if (t < 64) sbv[t] = Bv[(i * NO + o) * HH + t];
    __syncthreads();

    float acc[4][8][4];
    #pragma unroll
    for (int mt = 0; mt < 4; ++mt)
        #pragma unroll
        for (int nt = 0; nt < 8; ++nt) {
            acc[mt][nt][0] = 0.f; acc[mt][nt][1] = 0.f;
            acc[mt][nt][2] = 0.f; acc[mt][nt][3] = 0.f;
        }

    const uint32_t sA32 = smem_u32(sA);
    const uint32_t sB32 = smem_u32(sB);

    #pragma unroll
    for (int k = 0; k < 4; ++k) {
        uint32_t a[4][4];
        #pragma unroll
        for (int mt = 0; mt < 4; ++mt) {
            const int row = wid * 64 + mt * 16 + (lane & 15);
            const int ch  = (k * 2 + (lane >> 4)) ^ (row & 7);
            const uint32_t addr = sA32 + row * 128 + ch * 16;
            asm volatile("ldmatrix.sync.aligned.m8n8.x4.shared.b16 {%0,%1,%2,%3}, [%4];"
                : "=r"(a[mt][0]), "=r"(a[mt][1]), "=r"(a[mt][2]), "=r"(a[mt][3]) : "r"(addr));
        }
        uint32_t b[8][2];
        #pragma unroll
        for (int nt = 0; nt < 8; ++nt) {
            const int d  = k * 16 + (lane & 15);
            const int ch = nt ^ (d & 7);
            const uint32_t addr = sB32 + d * 128 + ch * 16;
            asm volatile("ldmatrix.sync.aligned.m8n8.x2.trans.shared.b16 {%0,%1}, [%2];"
                : "=r"(b[nt][0]), "=r"(b[nt][1]) : "r"(addr));
        }
        #pragma unroll
        for (int mt = 0; mt < 4; ++mt)
            #pragma unroll
            for (int nt = 0; nt < 8; ++nt)
                asm volatile("mma.sync.aligned.m16n8k16.row.col.f32.f16.f16.f32 "
                    "{%0,%1,%2,%3}, {%4,%5,%6,%7}, {%8,%9}, {%0,%1,%2,%3};"
                    : "+f"(acc[mt][nt][0]), "+f"(acc[mt][nt][1]),
                      "+f"(acc[mt][nt][2]), "+f"(acc[mt][nt][3])
                    : "r"(a[mt][0]), "r"(a[mt][1]), "r"(a[mt][2]), "r"(a[mt][3]),
                      "r"(b[nt][0]), "r"(b[nt][1]));
    }
    __syncthreads();

    __half2* stg = reinterpret_cast<__half2*>(sm);
    #pragma unroll
    for (int mt = 0; mt < 4; ++mt) {
        const int r0 = wid * 64 + mt * 16 + (lane >> 2);
        #pragma unroll
        for (int nt = 0; nt < 8; ++nt) {
            const int h = nt * 8 + (lane & 3) * 2;
            const float b0 = sbv[h], b1 = sbv[h + 1];
            stg[(r0 * 72 + h) >> 1] =
                __floats2half2_rn(acc[mt][nt][0] + b0, acc[mt][nt][1] + b1);
            stg[((r0 + 8) * 72 + h) >> 1] =
                __floats2half2_rn(acc[mt][nt][2] + b0, acc[mt][nt][3] + b1);
        }
    }
    __syncthreads();

    #pragma unroll
    for (int p = 0; p < 16; ++p) {
        const int n = p * 16 + (t >> 3), c = t & 7;
        const __half2 mk2 = __float2half2_rn(mask[n * NI + i]);
        uint4 v = *reinterpret_cast<const uint4*>(sm + n * 144 + c * 16);
        __half2* vh = reinterpret_cast<__half2*>(&v);
        vh[0] = __hmul2(vh[0], mk2); vh[1] = __hmul2(vh[1], mk2);
        vh[2] = __hmul2(vh[2], mk2); vh[3] = __hmul2(vh[3], mk2);
        *reinterpret_cast<uint4*>(g_votes + ((size_t)(n * NI + i) * NO + o) * HH + c * 8) = v;
    }
}

// ============================================================
// K3 (persistent tensorized routing): one block per n, all 3 iterations.
// Chunk = 8 i's (32 KB smem). Per iteration: one streaming read of votes.
//   agree  : mma.m16n8k16, votes rows x v(hi/lo fp16) in B col 0
//   softmax: SIMT, warp per i, lane per o
//   sum    : ldmatrix.x2.trans + mma.m16n8k8, c in B col 0, fp32 D in regs
// ============================================================
__global__ __launch_bounds__(256, 2) void k_route_all(float* __restrict__ out) {
    const int n = blockIdx.x;
    const int t = threadIdx.x, w = t >> 5, l = t & 31;

    __shared__ __align__(16) uint4  schunk[2048];   // 32 KB: row r = il*32+o, 8 sw chunks
    __shared__ __align__(16) __half svh[NO * HH];   // v hi
    __shared__ __align__(16) __half svl[NO * HH];   // v lo
    __shared__ float  sagree[NO * 8];
    __shared__ __half sct[NO * 8];                  // c[o][il] fp16
    __shared__ float  sai[NI];

    if (t < NI) sai[t] = g_ai[n * NI + t];

    const uint4* vb = reinterpret_cast<const uint4*>(g_votes) + (size_t)n * (NI * NO * HH / 8);
    const uint32_t cb = smem_u32(schunk);

    for (int it = 0; it < 3; ++it) {
        float acc[4][4][4];
        #pragma unroll
        for (int oi = 0; oi < 4; ++oi)
            #pragma unroll
            for (int ht = 0; ht < 4; ++ht) {
                acc[oi][ht][0] = 0.f; acc[oi][ht][1] = 0.f;
                acc[oi][ht][2] = 0.f; acc[oi][ht][3] = 0.f;
            }

        for (int chk = 0; chk < 16; ++chk) {
            __syncthreads();
            const uint4* src = vb + chk * 2048;
            #pragma unroll
            for (int j = 0; j < 8; ++j) {
                const int idx = t + j * 256;
                const int r = idx >> 3, c = idx & 7;
                schunk[(r << 3) | (c ^ (r >> 5))] = src[idx];
            }
            __syncthreads();

            if (it > 0) {
                // ---- agree: per warp, 4 owned o's
                #pragma unroll
                for (int oi = 0; oi < 4; ++oi) {
                    const int o = oi * 8 + w;
                    float d0 = 0.f, d1 = 0.f, d2 = 0.f, d3 = 0.f;
                    #pragma unroll
                    for (int k = 0; k < 4; ++k) {
                        const int il = l & 7;
                        const int r = il * 32 + o;
                        const int ch = (k * 2 + (l >> 4)) ^ il;
                        const uint32_t addr = cb + (((r << 3) + ch) << 4);
                        uint32_t a0, a1, a2, a3;
                        asm volatile("ldmatrix.sync.aligned.m8n8.x4.shared.b16 {%0,%1,%2,%3}, [%4];"
                            : "=r"(a0), "=r"(a1), "=r"(a2), "=r"(a3) : "r"(addr));
                        uint32_t b0 = 0, b1 = 0, c0 = 0, c1 = 0;
                        if (l < 4) {
                            b0 = *reinterpret_cast<const uint32_t*>(svh + o * 64 + k * 16 + l * 2);
                            b1 = *reinterpret_cast<const uint32_t*>(svh + o * 64 + k * 16 + 8 + l * 2);
                            c0 = *reinterpret_cast<const uint32_t*>(svl + o * 64 + k * 16 + l * 2);
                            c1 = *reinterpret_cast<const uint32_t*>(svl + o * 64 + k * 16 + 8 + l * 2);
                        }
                        asm volatile("mma.sync.aligned.m16n8k16.row.col.f32.f16.f16.f32 "
                            "{%0,%1,%2,%3}, {%4,%5,%6,%7}, {%8,%9}, {%0,%1,%2,%3};"
                            : "+f"(d0), "+f"(d1), "+f"(d2), "+f"(d3)
                            : "r"(a0), "r"(a1), "r"(a2), "r"(a3), "r"(b0), "r"(b1));
                        asm volatile("mma.sync.aligned.m16n8k16.row.col.f32.f16.f16.f32 "
                            "{%0,%1,%2,%3}, {%4,%5,%6,%7}, {%8,%9}, {%0,%1,%2,%3};"
                            : "+f"(d0), "+f"(d1), "+f"(d2), "+f"(d3)
                            : "r"(a0), "r"(a1), "r"(a2), "r"(a3), "r"(c0), "r"(c1));
                    }
                    if ((l & 3) == 0) sagree[o * 8 + (l >> 2)] = d0;
                }
                __syncthreads();

                // ---- b update + leaky softmax: warp w -> capsule i = chk*8+w, lane = o
                {
                    const int i = chk * 8 + w;
                    const float ag = sagree[l * 8 + w];
                    const size_t bix = ((size_t)(n * NI + i)) * NO + l;
                    float b = ag + (it == 2 ? g_b[bix] : 0.f);
                    if (it == 1) g_b[bix] = b;
                    float m = b;
                    #pragma unroll
                    for (int off = 16; off; off >>= 1)
                        m = fmaxf(m, __shfl_xor_sync(0xffffffffu, m, off));
                    m = fmaxf(m, 0.0f);
                    const float e = __expf(b - m);
                    float s = e;
                    #pragma unroll
                    for (int off = 16; off; off >>= 1)
                        s += __shfl_xor_sync(0xffffffffu, s, off);
                    s += __expf(-m);
                    sct[l * 8 + w] = __float2half(sai[i] * e / s);
                }
                __syncthreads();
            }

            // ---- weighted sum: s[o,h] += sum_i c[i,o] * votes[i,o,h]
            #pragma unroll
            for (int oi = 0; oi < 4; ++oi) {
                const int o = oi * 8 + w;
                uint32_t bf = 0;
                if (l < 4) {
                    if (it == 0) {
                        const float c0 = sai[chk * 8 + l * 2]     * (1.0f / 33.0f);
                        const float c1 = sai[chk * 8 + l * 2 + 1] * (1.0f / 33.0f);
                        const __half2 hc = __floats2half2_rn(c0, c1);
                        bf = *reinterpret_cast<const uint32_t*>(&hc);
                    } else {
                        bf = *reinterpret_cast<const uint32_t*>(sct + o * 8 + l * 2);
                    }
                }
                #pragma unroll
                for (int ht = 0; ht < 4; ++ht) {
                    const int il = l & 7;
                    const int hc = (ht * 2 + ((l >> 3) & 1)) ^ il;
                    const int r = il * 32 + o;
                    const uint32_t addr = cb + (((r << 3) + hc) << 4);
                    uint32_t t0, t1;
                    asm volatile("ldmatrix.sync.aligned.m8n8.x2.trans.shared.b16 {%0,%1}, [%2];"
                        : "=r"(t0), "=r"(t1) : "r"(addr));
                    asm volatile("mma.sync.aligned.m16n8k8.row.col.f32.f16.f16.f32 "
                        "{%0,%1,%2,%3}, {%4,%5}, {%6}, {%0,%1,%2,%3};"
                        : "+f"(acc[oi][ht][0]), "+f"(acc[oi][ht][1]),
                          "+f"(acc[oi][ht][2]), "+f"(acc[oi][ht][3])
                        : "r"(t0), "r"(t1), "r"(bf));
                }
            }
        } // chunks

        // ---- squash per o; write v (hi/lo) or final output
        #pragma unroll
        for (int oi = 0; oi < 4; ++oi) {
            const int o = oi * 8 + w;
            float q = 0.f;
            #pragma unroll
            for (int ht = 0; ht < 4; ++ht)
                q += acc[oi][ht][0] * acc[oi][ht][0] + acc[oi][ht][2] * acc[oi][ht][2];
            #pragma unroll
            for (int off = 16; off; off >>= 1)
                q += __shfl_xor_sync(0xffffffffu, q, off);
            const float nrm = sqrtf(q);
            const float f = (q / (q + 1.0f)) / (nrm + 1e-8f);

            if ((l & 3) == 0) {
                if (it < 2) {
                    #pragma unroll
                    for (int ht = 0; ht < 4; ++ht) {
                        const int h0 = ht * 16 + (l >> 2);
                        const float v0 = acc[oi][ht][0] * f;
                        const float v1 = acc[oi][ht][2] * f;
                        const __half hh0 = __float2half(v0);
                        const __half hh1 = __float2half(v1);
                        svh[o * 64 + h0] = hh0;
                        svl[o * 64 + h0] = __float2half(v0 - __half2float(hh0));
                        svh[o * 64 + h0 + 8] = hh1;
                        svl[o * 64 + h0 + 8] = __float2half(v1 - __half2float(hh1));
                    }
                } else {
                    #pragma unroll
                    for (int ht = 0; ht < 4; ++ht) {
                        const int h0 = ht * 16 + (l >> 2);
                        out[((size_t)n * NO + o) * HH + h0]     = acc[oi][ht][0] * f;
                        out[((size_t)n * NO + o) * HH + h0 + 8] = acc[oi][ht][2] * f;
                    }
                }
            }
        }
    } // iterations
}

// ============================================================
extern "C" void kernel_launch(void* const* d_in, const int* in_sizes, int n_in,
                              void* d_out, int out_size) {
    const float* x    = (const float*)d_in[0];
    const float* mask = (const float*)d_in[1];
    const float* Wcap = (const float*)d_in[2];
    const float* Bcap = (const float*)d_in[3];
    const float* Wv   = (const float*)d_in[4];
    const float* Bv   = (const float*)d_in[5];
    float* out = (float*)d_out;

    k_u        <<<dim3(8, 128),  256>>>(x, Wcap, Bcap);
    k_votes    <<<dim3(NO, NI),  128>>>(Wv, Bv, mask);
    k_route_all<<<NB, 256>>>(out);
}

// round 6
// speedup vs baseline: 1.8942x; 1.7945x over previous
#include <cuda_runtime.h>
#include <cuda_fp16.h>
#include <stdint.h>
#include <math.h>

#define NB 256   // batch
#define NI 128   // input capsules
#define DD 256   // input feature dim
#define NO 32    // output capsules
#define HH 64    // in_dim == out_dim

// ---- scratch (device globals; no allocation allowed) ----
__device__ __half g_votes[(size_t)NB * NI * NO * HH];  // [n][i][o][h] fp16, 134 MB
__device__ __half g_uh[(size_t)NB * NI * HH];          // squashed u fp16, 4 MB
__device__ float  g_ai[NB * NI];                       // ||u||
__device__ float  g_b[(size_t)NB * NI * NO];           // routing logits after iter-2

__device__ __forceinline__ uint32_t smem_u32(const void* p) {
    uint32_t a;
    asm("{ .reg .u64 t; cvta.to.shared.u64 t, %1; cvt.u32.u64 %0, t; }" : "=r"(a) : "l"(p));
    return a;
}

// ============================================================
// K1 (HMMA, hi/lo fp16 = fp32-accurate):
// u[n,i,:] = squash( x[n,i,:] @ Wcap[i] + Bcap[i] ) -> fp16, ai = ||u||
// block = (ntile of 128, i), 128 threads / 4 warps.
// A = x tile 128x64 per K-chunk (hi+lo), B = Wcap chunk 64x64 (hi+lo).
// D += Ahi*Bhi + Ahi*Blo + Alo*Bhi  (lo*lo negligible)
// ============================================================
__global__ __launch_bounds__(128) void k_u(const float* __restrict__ x,
                                           const float* __restrict__ Wcap,
                                           const float* __restrict__ Bcap) {
    __shared__ __align__(16) __half sAhi[128 * 64];   // 16 KB
    __shared__ __align__(16) __half sAlo[128 * 64];   // 16 KB
    __shared__ __align__(16) __half sBhi[64 * 64];    // 8 KB
    __shared__ __align__(16) __half sBlo[64 * 64];    // 8 KB

    const int i  = blockIdx.y;
    const int n0 = blockIdx.x * 128;
    const int t  = threadIdx.x, w = t >> 5, l = t & 31;

    __half2* sAhi2 = reinterpret_cast<__half2*>(sAhi);
    __half2* sAlo2 = reinterpret_cast<__half2*>(sAlo);
    __half2* sBhi2 = reinterpret_cast<__half2*>(sBhi);
    __half2* sBlo2 = reinterpret_cast<__half2*>(sBlo);
    const uint32_t aHi = smem_u32(sAhi), aLo = smem_u32(sAlo);
    const uint32_t bHi = smem_u32(sBhi), bLo = smem_u32(sBlo);

    float acc[2][8][4];
    #pragma unroll
    for (int mt = 0; mt < 2; ++mt)
        #pragma unroll
        for (int nt = 0; nt < 8; ++nt) {
            acc[mt][nt][0] = 0.f; acc[mt][nt][1] = 0.f;
            acc[mt][nt][2] = 0.f; acc[mt][nt][3] = 0.f;
        }

    for (int kc = 0; kc < 4; ++kc) {
        __syncthreads();
        // ---- A: x[n0..n0+127, i, kc*64..+63] fp32 -> hi/lo fp16, swizzled
        #pragma unroll
        for (int j = 0; j < 32; ++j) {
            const int idx = t + j * 128;           // 0..4095 (float2 units)
            const int r = idx >> 5, d2 = idx & 31;
            const float2 v = *reinterpret_cast<const float2*>(
                x + ((size_t)(n0 + r) * NI + i) * DD + kc * 64 + d2 * 2);
            const __half h0 = __float2half_rn(v.x), h1 = __float2half_rn(v.y);
            const __half l0 = __float2half_rn(v.x - __half2float(h0));
            const __half l1 = __float2half_rn(v.y - __half2float(h1));
            const int c = d2 >> 2;
            const int sidx = r * 32 + ((c ^ (r & 7)) << 2) + (d2 & 3);
            sAhi2[sidx] = __halves2half2(h0, h1);
            sAlo2[sidx] = __halves2half2(l0, l1);
        }
        // ---- B: Wcap[i][kc*64+d][h] fp32 -> hi/lo fp16, swizzled
        #pragma unroll
        for (int j = 0; j < 16; ++j) {
            const int idx = t + j * 128;           // 0..2047 (float2 units)
            const int d = idx >> 5, h2 = idx & 31;
            const float2 v = *reinterpret_cast<const float2*>(
                Wcap + (size_t)i * DD * HH + (size_t)(kc * 64 + d) * HH + h2 * 2);
            const __half h0 = __float2half_rn(v.x), h1 = __float2half_rn(v.y);
            const __half l0 = __float2half_rn(v.x - __half2float(h0));
            const __half l1 = __float2half_rn(v.y - __half2float(h1));
            const int c = h2 >> 2;
            const int sidx = d * 32 + ((c ^ (d & 7)) << 2) + (h2 & 3);
            sBhi2[sidx] = __halves2half2(h0, h1);
            sBlo2[sidx] = __halves2half2(l0, l1);
        }
        __syncthreads();

        #pragma unroll
        for (int k = 0; k < 4; ++k) {
            uint32_t ah[2][4], al[2][4];
            #pragma unroll
            for (int mt = 0; mt < 2; ++mt) {
                const int row = w * 32 + mt * 16 + (l & 15);
                const int ch  = (k * 2 + (l >> 4)) ^ (row & 7);
                const uint32_t off = row * 128 + ch * 16;
                asm volatile("ldmatrix.sync.aligned.m8n8.x4.shared.b16 {%0,%1,%2,%3}, [%4];"
                    : "=r"(ah[mt][0]), "=r"(ah[mt][1]), "=r"(ah[mt][2]), "=r"(ah[mt][3])
                    : "r"(aHi + off));
                asm volatile("ldmatrix.sync.aligned.m8n8.x4.shared.b16 {%0,%1,%2,%3}, [%4];"
                    : "=r"(al[mt][0]), "=r"(al[mt][1]), "=r"(al[mt][2]), "=r"(al[mt][3])
                    : "r"(aLo + off));
            }
            #pragma unroll
            for (int nt = 0; nt < 8; ++nt) {
                const int d  = k * 16 + (l & 15);
                const int ch = nt ^ (d & 7);
                const uint32_t off = d * 128 + ch * 16;
                uint32_t bh0, bh1, bl0, bl1;
                asm volatile("ldmatrix.sync.aligned.m8n8.x2.trans.shared.b16 {%0,%1}, [%2];"
                    : "=r"(bh0), "=r"(bh1) : "r"(bHi + off));
                asm volatile("ldmatrix.sync.aligned.m8n8.x2.trans.shared.b16 {%0,%1}, [%2];"
                    : "=r"(bl0), "=r"(bl1) : "r"(bLo + off));
                #pragma unroll
                for (int mt = 0; mt < 2; ++mt) {
                    asm volatile("mma.sync.aligned.m16n8k16.row.col.f32.f16.f16.f32 "
                        "{%0,%1,%2,%3}, {%4,%5,%6,%7}, {%8,%9}, {%0,%1,%2,%3};"
                        : "+f"(acc[mt][nt][0]), "+f"(acc[mt][nt][1]),
                          "+f"(acc[mt][nt][2]), "+f"(acc[mt][nt][3])
                        : "r"(ah[mt][0]), "r"(ah[mt][1]), "r"(ah[mt][2]), "r"(ah[mt][3]),
                          "r"(bh0), "r"(bh1));
                    asm volatile("mma.sync.aligned.m16n8k16.row.col.f32.f16.f16.f32 "
                        "{%0,%1,%2,%3}, {%4,%5,%6,%7}, {%8,%9}, {%0,%1,%2,%3};"
                        : "+f"(acc[mt][nt][0]), "+f"(acc[mt][nt][1]),
                          "+f"(acc[mt][nt][2]), "+f"(acc[mt][nt][3])
                        : "r"(ah[mt][0]), "r"(ah[mt][1]), "r"(ah[mt][2]), "r"(ah[mt][3]),
                          "r"(bl0), "r"(bl1));
                    asm volatile("mma.sync.aligned.m16n8k16.row.col.f32.f16.f16.f32 "
                        "{%0,%1,%2,%3}, {%4,%5,%6,%7}, {%8,%9}, {%0,%1,%2,%3};"
                        : "+f"(acc[mt][nt][0]), "+f"(acc[mt][nt][1]),
                          "+f"(acc[mt][nt][2]), "+f"(acc[mt][nt][3])
                        : "r"(al[mt][0]), "r"(al[mt][1]), "r"(al[mt][2]), "r"(al[mt][3]),
                          "r"(bh0), "r"(bh1));
                }
            }
        }
    }

    // ---- epilogue: +bias, squash per row, write u fp16 + ai
    #pragma unroll
    for (int mt = 0; mt < 2; ++mt) {
        const int r = w * 32 + mt * 16 + (l >> 2);
        float q0 = 0.f, q1 = 0.f;
        #pragma unroll
        for (int nt = 0; nt < 8; ++nt) {
            const float2 bv = *reinterpret_cast<const float2*>(
                Bcap + i * HH + nt * 8 + (l & 3) * 2);
            acc[mt][nt][0] += bv.x; acc[mt][nt][1] += bv.y;
            acc[mt][nt][2] += bv.x; acc[mt][nt][3] += bv.y;
            q0 += acc[mt][nt][0] * acc[mt][nt][0] + acc[mt][nt][1] * acc[mt][nt][1];
            q1 += acc[mt][nt][2] * acc[mt][nt][2] + acc[mt][nt][3] * acc[mt][nt][3];
        }
        q0 += __shfl_xor_sync(0xffffffffu, q0, 1);
        q0 += __shfl_xor_sync(0xffffffffu, q0, 2);
        q1 += __shfl_xor_sync(0xffffffffu, q1, 1);
        q1 += __shfl_xor_sync(0xffffffffu, q1, 2);
        const float nr0 = sqrtf(q0), nr1 = sqrtf(q1);
        const float f0 = (q0 / (q0 + 1.0f)) / (nr0 + 1e-8f);
        const float f1 = (q1 / (q1 + 1.0f)) / (nr1 + 1e-8f);

        __half* u0 = g_uh + ((size_t)(n0 + r) * NI + i) * HH;
        __half* u1 = g_uh + ((size_t)(n0 + r + 8) * NI + i) * HH;
        #pragma unroll
        for (int nt = 0; nt < 8; ++nt) {
            const int h = nt * 8 + (l & 3) * 2;
            *reinterpret_cast<__half2*>(u0 + h) =
                __floats2half2_rn(acc[mt][nt][0] * f0, acc[mt][nt][1] * f0);
            *reinterpret_cast<__half2*>(u1 + h) =
                __floats2half2_rn(acc[mt][nt][2] * f1, acc[mt][nt][3] * f1);
        }
        if ((l & 3) == 0) {
            g_ai[(n0 + r) * NI + i]     = f0 * nr0;
            g_ai[(n0 + r + 8) * NI + i] = f1 * nr1;
        }
    }
}

// ============================================================
// K2 (HMMA): votes[n,i,o,h] = fp16( mask * (u[:,i] @ Wv[i,o] + Bv) )
// ============================================================
__global__ __launch_bounds__(128) void k_votes(const float* __restrict__ Wv,
                                               const float* __restrict__ Bv,
                                               const float* __restrict__ mask) {
    __shared__ __align__(16) unsigned char sm[41216];
    const int o = blockIdx.x, i = blockIdx.y;
    const int t = threadIdx.x, wid = t >> 5, lane = t & 31;
    __half* sA = reinterpret_cast<__half*>(sm);           // 256 x 64 (32 KB)
    __half* sB = reinterpret_cast<__half*>(sm + 32768);   // 64 x 64  (8 KB)
    float*  sbv = reinterpret_cast<float*>(sm + 40960);   // bias (256 B)

    const uint4* usrc = reinterpret_cast<const uint4*>(g_uh) + (size_t)i * 8;
    #pragma unroll
    for (int idx = t; idx < 2048; idx += 128) {
        const int n = idx >> 3, c = idx & 7;
        uint4 v = usrc[(size_t)n * (NI * 8) + c];
        reinterpret_cast<uint4*>(sA)[n * 8 + (c ^ (n & 7))] = v;
    }
    const float2* wsrc = reinterpret_cast<const float2*>(Wv + ((size_t)(i * NO + o) << 12));
    #pragma unroll
    for (int idx = t; idx < 2048; idx += 128) {
        const int d = idx >> 5, hp = idx & 31;
        const float2 f = wsrc[idx];
        const __half2 hv = __floats2half2_rn(f.x, f.y);
        const int c = hp >> 2, w_ = hp & 3;
        reinterpret_cast<__half2*>(sB)[d * 32 + ((c ^ (d & 7)) << 2) + w_] = hv;
    }
    if (t < 64) sbv[t] = Bv[(i * NO + o) * HH + t];
    __syncthreads();

    float acc[4][8][4];
    #pragma unroll
    for (int mt = 0; mt < 4; ++mt)
        #pragma unroll
        for (int nt = 0; nt < 8; ++nt) {
            acc[mt][nt][0] = 0.f; acc[mt][nt][1] = 0.f;
            acc[mt][nt][2] = 0.f; acc[mt][nt][3] = 0.f;
        }

    const uint32_t sA32 = smem_u32(sA);
    const uint32_t sB32 = smem_u32(sB);

    #pragma unroll
    for (int k = 0; k < 4; ++k) {
        uint32_t a[4][4];
        #pragma unroll
        for (int mt = 0; mt < 4; ++mt) {
            const int row = wid * 64 + mt * 16 + (lane & 15);
            const int ch  = (k * 2 + (lane >> 4)) ^ (row & 7);
            const uint32_t addr = sA32 + row * 128 + ch * 16;
            asm volatile("ldmatrix.sync.aligned.m8n8.x4.shared.b16 {%0,%1,%2,%3}, [%4];"
                : "=r"(a[mt][0]), "=r"(a[mt][1]), "=r"(a[mt][2]), "=r"(a[mt][3]) : "r"(addr));
        }
        uint32_t b[8][2];
        #pragma unroll
        for (int nt = 0; nt < 8; ++nt) {
            const int d  = k * 16 + (lane & 15);
            const int ch = nt ^ (d & 7);
            const uint32_t addr = sB32 + d * 128 + ch * 16;
            asm volatile("ldmatrix.sync.aligned.m8n8.x2.trans.shared.b16 {%0,%1}, [%2];"
                : "=r"(b[nt][0]), "=r"(b[nt][1]) : "r"(addr));
        }
        #pragma unroll
        for (int mt = 0; mt < 4; ++mt)
            #pragma unroll
            for (int nt = 0; nt < 8; ++nt)
                asm volatile("mma.sync.aligned.m16n8k16.row.col.f32.f16.f16.f32 "
                    "{%0,%1,%2,%3}, {%4,%5,%6,%7}, {%8,%9}, {%0,%1,%2,%3};"
                    : "+f"(acc[mt][nt][0]), "+f"(acc[mt][nt][1]),
                      "+f"(acc[mt][nt][2]), "+f"(acc[mt][nt][3])
                    : "r"(a[mt][0]), "r"(a[mt][1]), "r"(a[mt][2]), "r"(a[mt][3]),
                      "r"(b[nt][0]), "r"(b[nt][1]));
    }
    __syncthreads();

    __half2* stg = reinterpret_cast<__half2*>(sm);
    #pragma unroll
    for (int mt = 0; mt < 4; ++mt) {
        const int r0 = wid * 64 + mt * 16 + (lane >> 2);
        #pragma unroll
        for (int nt = 0; nt < 8; ++nt) {
            const int h = nt * 8 + (lane & 3) * 2;
            const float b0 = sbv[h], b1 = sbv[h + 1];
            stg[(r0 * 72 + h) >> 1] =
                __floats2half2_rn(acc[mt][nt][0] + b0, acc[mt][nt][1] + b1);
            stg[((r0 + 8) * 72 + h) >> 1] =
                __floats2half2_rn(acc[mt][nt][2] + b0, acc[mt][nt][3] + b1);
        }
    }
    __syncthreads();

    #pragma unroll
    for (int p = 0; p < 16; ++p) {
        const int n = p * 16 + (t >> 3), c = t & 7;
        const __half2 mk2 = __float2half2_rn(mask[n * NI + i]);
        uint4 v = *reinterpret_cast<const uint4*>(sm + n * 144 + c * 16);
        __half2* vh = reinterpret_cast<__half2*>(&v);
        vh[0] = __hmul2(vh[0], mk2); vh[1] = __hmul2(vh[1], mk2);
        vh[2] = __hmul2(vh[2], mk2); vh[3] = __hmul2(vh[3], mk2);
        *reinterpret_cast<uint4*>(g_votes + ((size_t)(n * NI + i) * NO + o) * HH + c * 8) = v;
    }
}

// ============================================================
// K3 (persistent tensorized routing): one block per n, all 3 iterations.
// ============================================================
__global__ __launch_bounds__(256, 2) void k_route_all(float* __restrict__ out) {
    const int n = blockIdx.x;
    const int t = threadIdx.x, w = t >> 5, l = t & 31;

    __shared__ __align__(16) uint4  schunk[2048];   // 32 KB
    __shared__ __align__(16) __half svh[NO * HH];   // v hi
    __shared__ __align__(16) __half svl[NO * HH];   // v lo
    __shared__ float  sagree[NO * 8];
    __shared__ __half sct[NO * 8];                  // c[o][il] fp16
    __shared__ float  sai[NI];

    if (t < NI) sai[t] = g_ai[n * NI + t];

    const uint4* vb = reinterpret_cast<const uint4*>(g_votes) + (size_t)n * (NI * NO * HH / 8);
    const uint32_t cb = smem_u32(schunk);

    for (int it = 0; it < 3; ++it) {
        float acc[4][4][4];
        #pragma unroll
        for (int oi = 0; oi < 4; ++oi)
            #pragma unroll
            for (int ht = 0; ht < 4; ++ht) {
                acc[oi][ht][0] = 0.f; acc[oi][ht][1] = 0.f;
                acc[oi][ht][2] = 0.f; acc[oi][ht][3] = 0.f;
            }

        for (int chk = 0; chk < 16; ++chk) {
            __syncthreads();
            const uint4* src = vb + chk * 2048;
            #pragma unroll
            for (int j = 0; j < 8; ++j) {
                const int idx = t + j * 256;
                const int r = idx >> 3, c = idx & 7;
                schunk[(r << 3) | (c ^ (r >> 5))] = src[idx];
            }
            __syncthreads();

            if (it > 0) {
                #pragma unroll
                for (int oi = 0; oi < 4; ++oi) {
                    const int o = oi * 8 + w;
                    float d0 = 0.f, d1 = 0.f, d2 = 0.f, d3 = 0.f;
                    #pragma unroll
                    for (int k = 0; k < 4; ++k) {
                        const int il = l & 7;
                        const int r = il * 32 + o;
                        const int ch = (k * 2 + (l >> 4)) ^ il;
                        const uint32_t addr = cb + (((r << 3) + ch) << 4);
                        uint32_t a0, a1, a2, a3;
                        asm volatile("ldmatrix.sync.aligned.m8n8.x4.shared.b16 {%0,%1,%2,%3}, [%4];"
                            : "=r"(a0), "=r"(a1), "=r"(a2), "=r"(a3) : "r"(addr));
                        uint32_t b0 = 0, b1 = 0, c0 = 0, c1 = 0;
                        if (l < 4) {
                            b0 = *reinterpret_cast<const uint32_t*>(svh + o * 64 + k * 16 + l * 2);
                            b1 = *reinterpret_cast<const uint32_t*>(svh + o * 64 + k * 16 + 8 + l * 2);
                            c0 = *reinterpret_cast<const uint32_t*>(svl + o * 64 + k * 16 + l * 2);
                            c1 = *reinterpret_cast<const uint32_t*>(svl + o * 64 + k * 16 + 8 + l * 2);
                        }
                        asm volatile("mma.sync.aligned.m16n8k16.row.col.f32.f16.f16.f32 "
                            "{%0,%1,%2,%3}, {%4,%5,%6,%7}, {%8,%9}, {%0,%1,%2,%3};"
                            : "+f"(d0), "+f"(d1), "+f"(d2), "+f"(d3)
                            : "r"(a0), "r"(a1), "r"(a2), "r"(a3), "r"(b0), "r"(b1));
                        asm volatile("mma.sync.aligned.m16n8k16.row.col.f32.f16.f16.f32 "
                            "{%0,%1,%2,%3}, {%4,%5,%6,%7}, {%8,%9}, {%0,%1,%2,%3};"
                            : "+f"(d0), "+f"(d1), "+f"(d2), "+f"(d3)
                            : "r"(a0), "r"(a1), "r"(a2), "r"(a3), "r"(c0), "r"(c1));
                    }
                    if ((l & 3) == 0) sagree[o * 8 + (l >> 2)] = d0;
                }
                __syncthreads();

                {
                    const int i = chk * 8 + w;
                    const float ag = sagree[l * 8 + w];
                    const size_t bix = ((size_t)(n * NI + i)) * NO + l;
                    float b = ag + (it == 2 ? g_b[bix] : 0.f);
                    if (it == 1) g_b[bix] = b;
                    float m = b;
                    #pragma unroll
                    for (int off = 16; off; off >>= 1)
                        m = fmaxf(m, __shfl_xor_sync(0xffffffffu, m, off));
                    m = fmaxf(m, 0.0f);
                    const float e = __expf(b - m);
                    float s = e;
                    #pragma unroll
                    for (int off = 16; off; off >>= 1)
                        s += __shfl_xor_sync(0xffffffffu, s, off);
                    s += __expf(-m);
                    sct[l * 8 + w] = __float2half(sai[i] * e / s);
                }
                __syncthreads();
            }

            #pragma unroll
            for (int oi = 0; oi < 4; ++oi) {
                const int o = oi * 8 + w;
                uint32_t bf = 0;
                if (l < 4) {
                    if (it == 0) {
                        const float c0 = sai[chk * 8 + l * 2]     * (1.0f / 33.0f);
                        const float c1 = sai[chk * 8 + l * 2 + 1] * (1.0f / 33.0f);
                        const __half2 hc = __floats2half2_rn(c0, c1);
                        bf = *reinterpret_cast<const uint32_t*>(&hc);
                    } else {
                        bf = *reinterpret_cast<const uint32_t*>(sct + o * 8 + l * 2);
                    }
                }
                #pragma unroll
                for (int ht = 0; ht < 4; ++ht) {
                    const int il = l & 7;
                    const int hc = (ht * 2 + ((l >> 3) & 1)) ^ il;
                    const int r = il * 32 + o;
                    const uint32_t addr = cb + (((r << 3) + hc) << 4);
                    uint32_t t0, t1;
                    asm volatile("ldmatrix.sync.aligned.m8n8.x2.trans.shared.b16 {%0,%1}, [%2];"
                        : "=r"(t0), "=r"(t1) : "r"(addr));
                    asm volatile("mma.sync.aligned.m16n8k8.row.col.f32.f16.f16.f32 "
                        "{%0,%1,%2,%3}, {%4,%5}, {%6}, {%0,%1,%2,%3};"
                        : "+f"(acc[oi][ht][0]), "+f"(acc[oi][ht][1]),
                          "+f"(acc[oi][ht][2]), "+f"(acc[oi][ht][3])
                        : "r"(t0), "r"(t1), "r"(bf));
                }
            }
        } // chunks

        #pragma unroll
        for (int oi = 0; oi < 4; ++oi) {
            const int o = oi * 8 + w;
            float q = 0.f;
            #pragma unroll
            for (int ht = 0; ht < 4; ++ht)
                q += acc[oi][ht][0] * acc[oi][ht][0] + acc[oi][ht][2] * acc[oi][ht][2];
            #pragma unroll
            for (int off = 16; off; off >>= 1)
                q += __shfl_xor_sync(0xffffffffu, q, off);
            const float nrm = sqrtf(q);
            const float f = (q / (q + 1.0f)) / (nrm + 1e-8f);

            if ((l & 3) == 0) {
                if (it < 2) {
                    #pragma unroll
                    for (int ht = 0; ht < 4; ++ht) {
                        const int h0 = ht * 16 + (l >> 2);
                        const float v0 = acc[oi][ht][0] * f;
                        const float v1 = acc[oi][ht][2] * f;
                        const __half hh0 = __float2half(v0);
                        const __half hh1 = __float2half(v1);
                        svh[o * 64 + h0] = hh0;
                        svl[o * 64 + h0] = __float2half(v0 - __half2float(hh0));
                        svh[o * 64 + h0 + 8] = hh1;
                        svl[o * 64 + h0 + 8] = __float2half(v1 - __half2float(hh1));
                    }
                } else {
                    #pragma unroll
                    for (int ht = 0; ht < 4; ++ht) {
                        const int h0 = ht * 16 + (l >> 2);
                        out[((size_t)n * NO + o) * HH + h0]     = acc[oi][ht][0] * f;
                        out[((size_t)n * NO + o) * HH + h0 + 8] = acc[oi][ht][2] * f;
                    }
                }
            }
        }
    } // iterations
}

// ============================================================
extern "C" void kernel_launch(void* const* d_in, const int* in_sizes, int n_in,
                              void* d_out, int out_size) {
    const float* x    = (const float*)d_in[0];
    const float* mask = (const float*)d_in[1];
    const float* Wcap = (const float*)d_in[2];
    const float* Bcap = (const float*)d_in[3];
    const float* Wv   = (const float*)d_in[4];
    const float* Bv   = (const float*)d_in[5];
    float* out = (float*)d_out;

    k_u        <<<dim3(2, 128),  128>>>(x, Wcap, Bcap);
    k_votes    <<<dim3(NO, NI),  128>>>(Wv, Bv, mask);
    k_route_all<<<NB, 256>>>(out);
}

// round 7
// speedup vs baseline: 2.4460x; 1.2913x over previous
#include <cuda_runtime.h>
#include <cuda_fp16.h>
#include <stdint.h>
#include <math.h>

#define NB 256   // batch
#define NI 128   // input capsules
#define DD 256   // input feature dim
#define NO 32    // output capsules
#define HH 64    // in_dim == out_dim

// ---- scratch (device globals; no allocation allowed) ----
__device__ __half g_votes[(size_t)NB * NI * NO * HH];  // [n][i][o][h] fp16, 134 MB
__device__ __half g_uh[(size_t)NB * NI * HH];          // squashed u fp16, 4 MB
__device__ float  g_ai[NB * NI];                       // ||u||
__device__ float  g_b[(size_t)NB * NI * NO];           // routing logits after iter-2

__device__ __forceinline__ uint32_t smem_u32(const void* p) {
    uint32_t a;
    asm("{ .reg .u64 t; cvta.to.shared.u64 t, %1; cvt.u32.u64 %0, t; }" : "=r"(a) : "l"(p));
    return a;
}

#define CP_ASYNC16(dst_u32, src_ptr) \
    asm volatile("cp.async.cg.shared.global [%0], [%1], 16;" :: "r"(dst_u32), "l"(src_ptr))
#define CP_ASYNC_COMMIT() asm volatile("cp.async.commit_group;")
#define CP_ASYNC_WAIT1()  asm volatile("cp.async.wait_group 1;")
#define CP_ASYNC_WAIT0()  asm volatile("cp.async.wait_group 0;")

// ============================================================
// K1 (HMMA, hi/lo fp16 = fp32-accurate):
// u[n,i,:] = squash( x[n,i,:] @ Wcap[i] + Bcap[i] ) -> fp16, ai = ||u||
// ============================================================
__global__ __launch_bounds__(128) void k_u(const float* __restrict__ x,
                                           const float* __restrict__ Wcap,
                                           const float* __restrict__ Bcap) {
    __shared__ __align__(16) __half sAhi[128 * 64];
    __shared__ __align__(16) __half sAlo[128 * 64];
    __shared__ __align__(16) __half sBhi[64 * 64];
    __shared__ __align__(16) __half sBlo[64 * 64];

    const int i  = blockIdx.y;
    const int n0 = blockIdx.x * 128;
    const int t  = threadIdx.x, w = t >> 5, l = t & 31;

    __half2* sAhi2 = reinterpret_cast<__half2*>(sAhi);
    __half2* sAlo2 = reinterpret_cast<__half2*>(sAlo);
    __half2* sBhi2 = reinterpret_cast<__half2*>(sBhi);
    __half2* sBlo2 = reinterpret_cast<__half2*>(sBlo);
    const uint32_t aHi = smem_u32(sAhi), aLo = smem_u32(sAlo);
    const uint32_t bHi = smem_u32(sBhi), bLo = smem_u32(sBlo);

    float acc[2][8][4];
    #pragma unroll
    for (int mt = 0; mt < 2; ++mt)
        #pragma unroll
        for (int nt = 0; nt < 8; ++nt) {
            acc[mt][nt][0] = 0.f; acc[mt][nt][1] = 0.f;
            acc[mt][nt][2] = 0.f; acc[mt][nt][3] = 0.f;
        }

    for (int kc = 0; kc < 4; ++kc) {
        __syncthreads();
        #pragma unroll
        for (int j = 0; j < 32; ++j) {
            const int idx = t + j * 128;
            const int r = idx >> 5, d2 = idx & 31;
            const float2 v = *reinterpret_cast<const float2*>(
                x + ((size_t)(n0 + r) * NI + i) * DD + kc * 64 + d2 * 2);
            const __half h0 = __float2half_rn(v.x), h1 = __float2half_rn(v.y);
            const __half l0 = __float2half_rn(v.x - __half2float(h0));
            const __half l1 = __float2half_rn(v.y - __half2float(h1));
            const int c = d2 >> 2;
            const int sidx = r * 32 + ((c ^ (r & 7)) << 2) + (d2 & 3);
            sAhi2[sidx] = __halves2half2(h0, h1);
            sAlo2[sidx] = __halves2half2(l0, l1);
        }
        #pragma unroll
        for (int j = 0; j < 16; ++j) {
            const int idx = t + j * 128;
            const int d = idx >> 5, h2 = idx & 31;
            const float2 v = *reinterpret_cast<const float2*>(
                Wcap + (size_t)i * DD * HH + (size_t)(kc * 64 + d) * HH + h2 * 2);
            const __half h0 = __float2half_rn(v.x), h1 = __float2half_rn(v.y);
            const __half l0 = __float2half_rn(v.x - __half2float(h0));
            const __half l1 = __float2half_rn(v.y - __half2float(h1));
            const int c = h2 >> 2;
            const int sidx = d * 32 + ((c ^ (d & 7)) << 2) + (h2 & 3);
            sBhi2[sidx] = __halves2half2(h0, h1);
            sBlo2[sidx] = __halves2half2(l0, l1);
        }
        __syncthreads();

        #pragma unroll
        for (int k = 0; k < 4; ++k) {
            uint32_t ah[2][4], al[2][4];
            #pragma unroll
            for (int mt = 0; mt < 2; ++mt) {
                const int row = w * 32 + mt * 16 + (l & 15);
                const int ch  = (k * 2 + (l >> 4)) ^ (row & 7);
                const uint32_t off = row * 128 + ch * 16;
                asm volatile("ldmatrix.sync.aligned.m8n8.x4.shared.b16 {%0,%1,%2,%3}, [%4];"
                    : "=r"(ah[mt][0]), "=r"(ah[mt][1]), "=r"(ah[mt][2]), "=r"(ah[mt][3])
                    : "r"(aHi + off));
                asm volatile("ldmatrix.sync.aligned.m8n8.x4.shared.b16 {%0,%1,%2,%3}, [%4];"
                    : "=r"(al[mt][0]), "=r"(al[mt][1]), "=r"(al[mt][2]), "=r"(al[mt][3])
                    : "r"(aLo + off));
            }
            #pragma unroll
            for (int nt = 0; nt < 8; ++nt) {
                const int d  = k * 16 + (l & 15);
                const int ch = nt ^ (d & 7);
                const uint32_t off = d * 128 + ch * 16;
                uint32_t bh0, bh1, bl0, bl1;
                asm volatile("ldmatrix.sync.aligned.m8n8.x2.trans.shared.b16 {%0,%1}, [%2];"
                    : "=r"(bh0), "=r"(bh1) : "r"(bHi + off));
                asm volatile("ldmatrix.sync.aligned.m8n8.x2.trans.shared.b16 {%0,%1}, [%2];"
                    : "=r"(bl0), "=r"(bl1) : "r"(bLo + off));
                #pragma unroll
                for (int mt = 0; mt < 2; ++mt) {
                    asm volatile("mma.sync.aligned.m16n8k16.row.col.f32.f16.f16.f32 "
                        "{%0,%1,%2,%3}, {%4,%5,%6,%7}, {%8,%9}, {%0,%1,%2,%3};"
                        : "+f"(acc[mt][nt][0]), "+f"(acc[mt][nt][1]),
                          "+f"(acc[mt][nt][2]), "+f"(acc[mt][nt][3])
                        : "r"(ah[mt][0]), "r"(ah[mt][1]), "r"(ah[mt][2]), "r"(ah[mt][3]),
                          "r"(bh0), "r"(bh1));
                    asm volatile("mma.sync.aligned.m16n8k16.row.col.f32.f16.f16.f32 "
                        "{%0,%1,%2,%3}, {%4,%5,%6,%7}, {%8,%9}, {%0,%1,%2,%3};"
                        : "+f"(acc[mt][nt][0]), "+f"(acc[mt][nt][1]),
                          "+f"(acc[mt][nt][2]), "+f"(acc[mt][nt][3])
                        : "r"(ah[mt][0]), "r"(ah[mt][1]), "r"(ah[mt][2]), "r"(ah[mt][3]),
                          "r"(bl0), "r"(bl1));
                    asm volatile("mma.sync.aligned.m16n8k16.row.col.f32.f16.f16.f32 "
                        "{%0,%1,%2,%3}, {%4,%5,%6,%7}, {%8,%9}, {%0,%1,%2,%3};"
                        : "+f"(acc[mt][nt][0]), "+f"(acc[mt][nt][1]),
                          "+f"(acc[mt][nt][2]), "+f"(acc[mt][nt][3])
                        : "r"(al[mt][0]), "r"(al[mt][1]), "r"(al[mt][2]), "r"(al[mt][3]),
                          "r"(bh0), "r"(bh1));
                }
            }
        }
    }

    #pragma unroll
    for (int mt = 0; mt < 2; ++mt) {
        const int r = w * 32 + mt * 16 + (l >> 2);
        float q0 = 0.f, q1 = 0.f;
        #pragma unroll
        for (int nt = 0; nt < 8; ++nt) {
            const float2 bv = *reinterpret_cast<const float2*>(
                Bcap + i * HH + nt * 8 + (l & 3) * 2);
            acc[mt][nt][0] += bv.x; acc[mt][nt][1] += bv.y;
            acc[mt][nt][2] += bv.x; acc[mt][nt][3] += bv.y;
            q0 += acc[mt][nt][0] * acc[mt][nt][0] + acc[mt][nt][1] * acc[mt][nt][1];
            q1 += acc[mt][nt][2] * acc[mt][nt][2] + acc[mt][nt][3] * acc[mt][nt][3];
        }
        q0 += __shfl_xor_sync(0xffffffffu, q0, 1);
        q0 += __shfl_xor_sync(0xffffffffu, q0, 2);
        q1 += __shfl_xor_sync(0xffffffffu, q1, 1);
        q1 += __shfl_xor_sync(0xffffffffu, q1, 2);
        const float nr0 = sqrtf(q0), nr1 = sqrtf(q1);
        const float f0 = (q0 / (q0 + 1.0f)) / (nr0 + 1e-8f);
        const float f1 = (q1 / (q1 + 1.0f)) / (nr1 + 1e-8f);

        __half* u0 = g_uh + ((size_t)(n0 + r) * NI + i) * HH;
        __half* u1 = g_uh + ((size_t)(n0 + r + 8) * NI + i) * HH;
        #pragma unroll
        for (int nt = 0; nt < 8; ++nt) {
            const int h = nt * 8 + (l & 3) * 2;
            *reinterpret_cast<__half2*>(u0 + h) =
                __floats2half2_rn(acc[mt][nt][0] * f0, acc[mt][nt][1] * f0);
            *reinterpret_cast<__half2*>(u1 + h) =
                __floats2half2_rn(acc[mt][nt][2] * f1, acc[mt][nt][3] * f1);
        }
        if ((l & 3) == 0) {
            g_ai[(n0 + r) * NI + i]     = f0 * nr0;
            g_ai[(n0 + r + 8) * NI + i] = f1 * nr1;
        }
    }
}

// ============================================================
// K2 (HMMA): votes[n,i,o,h] = fp16( mask * (u[:,i] @ Wv[i,o] + Bv) )
// ============================================================
__global__ __launch_bounds__(128) void k_votes(const float* __restrict__ Wv,
                                               const float* __restrict__ Bv,
                                               const float* __restrict__ mask) {
    __shared__ __align__(16) unsigned char sm[41216];
    const int o = blockIdx.x, i = blockIdx.y;
    const int t = threadIdx.x, wid = t >> 5, lane = t & 31;
    __half* sA = reinterpret_cast<__half*>(sm);
    __half* sB = reinterpret_cast<__half*>(sm + 32768);
    float*  sbv = reinterpret_cast<float*>(sm + 40960);

    const uint4* usrc = reinterpret_cast<const uint4*>(g_uh) + (size_t)i * 8;
    #pragma unroll
    for (int idx = t; idx < 2048; idx += 128) {
        const int n = idx >> 3, c = idx & 7;
        uint4 v = usrc[(size_t)n * (NI * 8) + c];
        reinterpret_cast<uint4*>(sA)[n * 8 + (c ^ (n & 7))] = v;
    }
    const float2* wsrc = reinterpret_cast<const float2*>(Wv + ((size_t)(i * NO + o) << 12));
    #pragma unroll
    for (int idx = t; idx < 2048; idx += 128) {
        const int d = idx >> 5, hp = idx & 31;
        const float2 f = wsrc[idx];
        const __half2 hv = __floats2half2_rn(f.x, f.y);
        const int c = hp >> 2, w_ = hp & 3;
        reinterpret_cast<__half2*>(sB)[d * 32 + ((c ^ (d & 7)) << 2) + w_] = hv;
    }
    if (t < 64) sbv[t] = Bv[(i * NO + o) * HH + t];
    __syncthreads();

    float acc[4][8][4];
    #pragma unroll
    for (int mt = 0; mt < 4; ++mt)
        #pragma unroll
        for (int nt = 0; nt < 8; ++nt) {
            acc[mt][nt][0] = 0.f; acc[mt][nt][1] = 0.f;
            acc[mt][nt][2] = 0.f; acc[mt][nt][3] = 0.f;
        }

    const uint32_t sA32 = smem_u32(sA);
    const uint32_t sB32 = smem_u32(sB);

    #pragma unroll
    for (int k = 0; k < 4; ++k) {
        uint32_t a[4][4];
        #pragma unroll
        for (int mt = 0; mt < 4; ++mt) {
            const int row = wid * 64 + mt * 16 + (lane & 15);
            const int ch  = (k * 2 + (lane >> 4)) ^ (row & 7);
            const uint32_t addr = sA32 + row * 128 + ch * 16;
            asm volatile("ldmatrix.sync.aligned.m8n8.x4.shared.b16 {%0,%1,%2,%3}, [%4];"
                : "=r"(a[mt][0]), "=r"(a[mt][1]), "=r"(a[mt][2]), "=r"(a[mt][3]) : "r"(addr));
        }
        uint32_t b[8][2];
        #pragma unroll
        for (int nt = 0; nt < 8; ++nt) {
            const int d  = k * 16 + (lane & 15);
            const int ch = nt ^ (d & 7);
            const uint32_t addr = sB32 + d * 128 + ch * 16;
            asm volatile("ldmatrix.sync.aligned.m8n8.x2.trans.shared.b16 {%0,%1}, [%2];"
                : "=r"(b[nt][0]), "=r"(b[nt][1]) : "r"(addr));
        }
        #pragma unroll
        for (int mt = 0; mt < 4; ++mt)
            #pragma unroll
            for (int nt = 0; nt < 8; ++nt)
                asm volatile("mma.sync.aligned.m16n8k16.row.col.f32.f16.f16.f32 "
                    "{%0,%1,%2,%3}, {%4,%5,%6,%7}, {%8,%9}, {%0,%1,%2,%3};"
                    : "+f"(acc[mt][nt][0]), "+f"(acc[mt][nt][1]),
                      "+f"(acc[mt][nt][2]), "+f"(acc[mt][nt][3])
                    : "r"(a[mt][0]), "r"(a[mt][1]), "r"(a[mt][2]), "r"(a[mt][3]),
                      "r"(b[nt][0]), "r"(b[nt][1]));
    }
    __syncthreads();

    __half2* stg = reinterpret_cast<__half2*>(sm);
    #pragma unroll
    for (int mt = 0; mt < 4; ++mt) {
        const int r0 = wid * 64 + mt * 16 + (lane >> 2);
        #pragma unroll
        for (int nt = 0; nt < 8; ++nt) {
            const int h = nt * 8 + (lane & 3) * 2;
            const float b0 = sbv[h], b1 = sbv[h + 1];
            stg[(r0 * 72 + h) >> 1] =
                __floats2half2_rn(acc[mt][nt][0] + b0, acc[mt][nt][1] + b1);
            stg[((r0 + 8) * 72 + h) >> 1] =
                __floats2half2_rn(acc[mt][nt][2] + b0, acc[mt][nt][3] + b1);
        }
    }
    __syncthreads();

    #pragma unroll
    for (int p = 0; p < 16; ++p) {
        const int n = p * 16 + (t >> 3), c = t & 7;
        const __half2 mk2 = __float2half2_rn(mask[n * NI + i]);
        uint4 v = *reinterpret_cast<const uint4*>(sm + n * 144 + c * 16);
        __half2* vh = reinterpret_cast<__half2*>(&v);
        vh[0] = __hmul2(vh[0], mk2); vh[1] = __hmul2(vh[1], mk2);
        vh[2] = __hmul2(vh[2], mk2); vh[3] = __hmul2(vh[3], mk2);
        *reinterpret_cast<uint4*>(g_votes + ((size_t)(n * NI + i) * NO + o) * HH + c * 8) = v;
    }
}

// ============================================================
// K3 (persistent tensorized routing, cp.async double-buffered):
// one block per n, all 3 iterations; votes streamed 32KB chunks ping-pong.
// ============================================================
__global__ __launch_bounds__(256, 2) void k_route_all(float* __restrict__ out) {
    extern __shared__ __align__(16) uint4 dynbuf[];     // 2 x 2048 uint4 = 64 KB
    __shared__ __align__(16) __half svh[NO * HH];
    __shared__ __align__(16) __half svl[NO * HH];
    __shared__ float  sagree[NO * 8];
    __shared__ __half sct[NO * 8];
    __shared__ float  sai[NI];

    const int n = blockIdx.x;
    const int t = threadIdx.x, w = t >> 5, l = t & 31;

    if (t < NI) sai[t] = g_ai[n * NI + t];

    const uint4* vb = reinterpret_cast<const uint4*>(g_votes) + (size_t)n * (NI * NO * HH / 8);
    const uint32_t cb0 = smem_u32(dynbuf);
    const uint32_t cb1 = smem_u32(dynbuf + 2048);

    for (int it = 0; it < 3; ++it) {
        float acc[4][4][4];
        #pragma unroll
        for (int oi = 0; oi < 4; ++oi)
            #pragma unroll
            for (int ht = 0; ht < 4; ++ht) {
                acc[oi][ht][0] = 0.f; acc[oi][ht][1] = 0.f;
                acc[oi][ht][2] = 0.f; acc[oi][ht][3] = 0.f;
            }

        // prefetch chunk 0 -> buf0
        {
            const uint4* src = vb;
            #pragma unroll
            for (int j = 0; j < 8; ++j) {
                const int idx = t + j * 256;
                const int r = idx >> 3, c = idx & 7;
                CP_ASYNC16(cb0 + (((r << 3) | (c ^ (r >> 5))) << 4), src + idx);
            }
            CP_ASYNC_COMMIT();
        }

        #pragma unroll 1
        for (int chk = 0; chk < 16; ++chk) {
            const uint32_t cb = (chk & 1) ? cb1 : cb0;
            // issue prefetch of chunk chk+1 into the other buffer
            if (chk < 15) {
                const uint32_t cbn = (chk & 1) ? cb0 : cb1;
                const uint4* src = vb + (chk + 1) * 2048;
                #pragma unroll
                for (int j = 0; j < 8; ++j) {
                    const int idx = t + j * 256;
                    const int r = idx >> 3, c = idx & 7;
                    CP_ASYNC16(cbn + (((r << 3) | (c ^ (r >> 5))) << 4), src + idx);
                }
                CP_ASYNC_COMMIT();
                CP_ASYNC_WAIT1();
            } else {
                CP_ASYNC_WAIT0();
            }
            __syncthreads();   // chunk chk resident in cb

            if (it > 0) {
                #pragma unroll
                for (int oi = 0; oi < 4; ++oi) {
                    const int o = oi * 8 + w;
                    float d0 = 0.f, d1 = 0.f, d2 = 0.f, d3 = 0.f;
                    #pragma unroll
                    for (int k = 0; k < 4; ++k) {
                        const int il = l & 7;
                        const int r = il * 32 + o;
                        const int ch = (k * 2 + (l >> 4)) ^ il;
                        const uint32_t addr = cb + (((r << 3) + ch) << 4);
                        uint32_t a0, a1, a2, a3;
                        asm volatile("ldmatrix.sync.aligned.m8n8.x4.shared.b16 {%0,%1,%2,%3}, [%4];"
                            : "=r"(a0), "=r"(a1), "=r"(a2), "=r"(a3) : "r"(addr));
                        uint32_t b0 = 0, b1 = 0, c0 = 0, c1 = 0;
                        if (l < 4) {
                            b0 = *reinterpret_cast<const uint32_t*>(svh + o * 64 + k * 16 + l * 2);
                            b1 = *reinterpret_cast<const uint32_t*>(svh + o * 64 + k * 16 + 8 + l * 2);
                            c0 = *reinterpret_cast<const uint32_t*>(svl + o * 64 + k * 16 + l * 2);
                            c1 = *reinterpret_cast<const uint32_t*>(svl + o * 64 + k * 16 + 8 + l * 2);
                        }
                        asm volatile("mma.sync.aligned.m16n8k16.row.col.f32.f16.f16.f32 "
                            "{%0,%1,%2,%3}, {%4,%5,%6,%7}, {%8,%9}, {%0,%1,%2,%3};"
                            : "+f"(d0), "+f"(d1), "+f"(d2), "+f"(d3)
                            : "r"(a0), "r"(a1), "r"(a2), "r"(a3), "r"(b0), "r"(b1));
                        asm volatile("mma.sync.aligned.m16n8k16.row.col.f32.f16.f16.f32 "
                            "{%0,%1,%2,%3}, {%4,%5,%6,%7}, {%8,%9}, {%0,%1,%2,%3};"
                            : "+f"(d0), "+f"(d1), "+f"(d2), "+f"(d3)
                            : "r"(a0), "r"(a1), "r"(a2), "r"(a3), "r"(c0), "r"(c1));
                    }
                    if ((l & 3) == 0) sagree[o * 8 + (l >> 2)] = d0;
                }
                __syncthreads();

                {
                    const int i = chk * 8 + w;
                    const float ag = sagree[l * 8 + w];
                    const size_t bix = ((size_t)(n * NI + i)) * NO + l;
                    float b = ag + (it == 2 ? g_b[bix] : 0.f);
                    if (it == 1) g_b[bix] = b;
                    float m = b;
                    #pragma unroll
                    for (int off = 16; off; off >>= 1)
                        m = fmaxf(m, __shfl_xor_sync(0xffffffffu, m, off));
                    m = fmaxf(m, 0.0f);
                    const float e = __expf(b - m);
                    float s = e;
                    #pragma unroll
                    for (int off = 16; off; off >>= 1)
                        s += __shfl_xor_sync(0xffffffffu, s, off);
                    s += __expf(-m);
                    sct[l * 8 + w] = __float2half(sai[i] * e / s);
                }
                __syncthreads();
            }

            #pragma unroll
            for (int oi = 0; oi < 4; ++oi) {
                const int o = oi * 8 + w;
                uint32_t bf = 0;
                if (l < 4) {
                    if (it == 0) {
                        const float c0 = sai[chk * 8 + l * 2]     * (1.0f / 33.0f);
                        const float c1 = sai[chk * 8 + l * 2 + 1] * (1.0f / 33.0f);
                        const __half2 hc = __floats2half2_rn(c0, c1);
                        bf = *reinterpret_cast<const uint32_t*>(&hc);
                    } else {
                        bf = *reinterpret_cast<const uint32_t*>(sct + o * 8 + l * 2);
                    }
                }
                #pragma unroll
                for (int ht = 0; ht < 4; ++ht) {
                    const int il = l & 7;
                    const int hc = (ht * 2 + ((l >> 3) & 1)) ^ il;
                    const int r = il * 32 + o;
                    const uint32_t addr = cb + (((r << 3) + hc) << 4);
                    uint32_t t0, t1;
                    asm volatile("ldmatrix.sync.aligned.m8n8.x2.trans.shared.b16 {%0,%1}, [%2];"
                        : "=r"(t0), "=r"(t1) : "r"(addr));
                    asm volatile("mma.sync.aligned.m16n8k8.row.col.f32.f16.f16.f32 "
                        "{%0,%1,%2,%3}, {%4,%5}, {%6}, {%0,%1,%2,%3};"
                        : "+f"(acc[oi][ht][0]), "+f"(acc[oi][ht][1]),
                          "+f"(acc[oi][ht][2]), "+f"(acc[oi][ht][3])
                        : "r"(t0), "r"(t1), "r"(bf));
                }
            }
            __syncthreads();   // all reads of cb done before it is refilled
        } // chunks

        #pragma unroll
        for (int oi = 0; oi < 4; ++oi) {
            const int o = oi * 8 + w;
            float q = 0.f;
            #pragma unroll
            for (int ht = 0; ht < 4; ++ht)
                q += acc[oi][ht][0] * acc[oi][ht][0] + acc[oi][ht][2] * acc[oi][ht][2];
            #pragma unroll
            for (int off = 16; off; off >>= 1)
                q += __shfl_xor_sync(0xffffffffu, q, off);
            const float nrm = sqrtf(q);
            const float f = (q / (q + 1.0f)) / (nrm + 1e-8f);

            if ((l & 3) == 0) {
                if (it < 2) {
                    #pragma unroll
                    for (int ht = 0; ht < 4; ++ht) {
                        const int h0 = ht * 16 + (l >> 2);
                        const float v0 = acc[oi][ht][0] * f;
                        const float v1 = acc[oi][ht][2] * f;
                        const __half hh0 = __float2half(v0);
                        const __half hh1 = __float2half(v1);
                        svh[o * 64 + h0] = hh0;
                        svl[o * 64 + h0] = __float2half(v0 - __half2float(hh0));
                        svh[o * 64 + h0 + 8] = hh1;
                        svl[o * 64 + h0 + 8] = __float2half(v1 - __half2float(hh1));
                    }
                } else {
                    #pragma unroll
                    for (int ht = 0; ht < 4; ++ht) {
                        const int h0 = ht * 16 + (l >> 2);
                        out[((size_t)n * NO + o) * HH + h0]     = acc[oi][ht][0] * f;
                        out[((size_t)n * NO + o) * HH + h0 + 8] = acc[oi][ht][2] * f;
                    }
                }
            }
        }
    } // iterations
}

// ============================================================
extern "C" void kernel_launch(void* const* d_in, const int* in_sizes, int n_in,
                              void* d_out, int out_size) {
    const float* x    = (const float*)d_in[0];
    const float* mask = (const float*)d_in[1];
    const float* Wcap = (const float*)d_in[2];
    const float* Bcap = (const float*)d_in[3];
    const float* Wv   = (const float*)d_in[4];
    const float* Bv   = (const float*)d_in[5];
    float* out = (float*)d_out;

    cudaFuncSetAttribute(k_route_all, cudaFuncAttributeMaxDynamicSharedMemorySize, 65536);

    k_u        <<<dim3(2, 128),  128>>>(x, Wcap, Bcap);
    k_votes    <<<dim3(NO, NI),  128>>>(Wv, Bv, mask);
    k_route_all<<<NB, 256, 65536>>>(out);
}